// round 10
// baseline (speedup 1.0000x reference)
#include <cuda_runtime.h>
#include <cuda_fp16.h>
#include <cstdint>

// ============================================================================
// Problem constants
// ============================================================================
#define T_TOKENS 4096
#define IN_F     4096
#define OUT_F    4096
#define NNZ      512

// GEMM tiling: CTA 128x128, warp tile 64x32 (8 warps, 2x4), 2 CTAs/SM.
static constexpr int BM = 128;
static constexpr int BN = 128;
static constexpr int BK = 64;                 // fp16 -> 128B rows (SW128 atom)
static constexpr int KITERS = IN_F / BK;      // 64
static constexpr int STAGES = 3;
static constexpr int STAGE_BYTES = (BM * BK + BN * BK) * 2;  // 32768
static constexpr int MBAR_BASE  = STAGES * STAGE_BYTES;      // 98304
static constexpr int SMEM_TOTAL = MBAR_BASE + 64;            // 98368

// Fused-grid layout. Prep blocks first (in-order dispatch => all prep blocks
// are handed out before any GEMM block), GEMM tiles last.
//   Conversion: 4096 blocks, 4 tokens each (block c -> x panel c>>5, 32/panel)
//   Densify:    4096 blocks, 1 W row each (row o -> W panel o>>7, 128/panel)
// Early-needed-first prep order (wave-1 GEMM corner needs x panels 0-16 and
// W panels 0-17):
static constexpr int NPANEL = 32;
static constexpr int DENS_EARLY = 18 * 128;                  // 2304 rows
static constexpr int CONV_EARLY = 17 * 32;                   // 544 blocks
static constexpr int B0_CONV_EARLY = DENS_EARLY;             // 2304
static constexpr int B0_CONV_REST  = B0_CONV_EARLY + CONV_EARLY;   // 2848
static constexpr int B0_DENS_REST  = B0_CONV_REST + (4096 - CONV_EARLY); // 6400
static constexpr int B0_GEMM       = 8192;
static constexpr int GRID          = B0_GEMM + 1024;         // 9216

// ============================================================================
// Scratch (device globals — no allocation allowed)
// ============================================================================
__device__ __align__(16) __half g_xh[(size_t)T_TOKENS * IN_F];  // 32 MB fp16 x
__device__ __align__(16) __half g_wh[(size_t)OUT_F * IN_F];     // 32 MB fp16 dense W
__device__ int g_xready[NPANEL];  // conv blocks done per x panel  (target 32)
__device__ int g_wready[NPANEL];  // densify rows done per W panel (target 128)

// ============================================================================
// Helpers
// ============================================================================
__device__ __forceinline__ uint32_t smem_u32(const void* p) {
    uint32_t a;
    asm("{ .reg .u64 t; cvta.to.shared.u64 t, %1; cvt.u32.u64 %0, t; }"
        : "=r"(a) : "l"(p));
    return a;
}
#define SW128(o) ((o) ^ (((o) >> 3) & 0x70))

__device__ __forceinline__ void cp_async16(uint32_t dst, const void* src) {
    asm volatile("cp.async.cg.shared.global [%0], [%1], 16;" :: "r"(dst), "l"(src));
}
__device__ __forceinline__ void cp_async_mbar_arrive(uint32_t mbar) {
    asm volatile("cp.async.mbarrier.arrive.noinc.shared.b64 [%0];"
                 :: "r"(mbar) : "memory");
}
__device__ __forceinline__ void mbar_init(uint32_t mbar, uint32_t cnt) {
    asm volatile("mbarrier.init.shared.b64 [%0], %1;" :: "r"(mbar), "r"(cnt)
                 : "memory");
}
__device__ __forceinline__ void mbar_arrive(uint32_t mbar) {
    asm volatile("mbarrier.arrive.release.cta.shared::cta.b64 _, [%0];"
                 :: "r"(mbar) : "memory");
}
__device__ __forceinline__ void mbar_wait(uint32_t mbar, uint32_t parity) {
    uint32_t done;
    asm volatile("{ .reg .pred p;\n\t"
        "mbarrier.try_wait.parity.acquire.cta.shared::cta.b64 p, [%1], %2;\n\t"
        "selp.b32 %0, 1, 0, p; }"
        : "=r"(done) : "r"(mbar), "r"(parity) : "memory");
    if (!done) {
        asm volatile("{ .reg .pred P1;\n\t"
            "WAIT_LOOP_%=:\n\t"
            "mbarrier.try_wait.parity.acquire.cta.shared::cta.b64 P1, [%0], %1, 0x989680;\n\t"
            "@P1 bra.uni WAIT_DONE_%=;\n\t"
            "bra.uni WAIT_LOOP_%=;\n\t"
            "WAIT_DONE_%=: }"
            :: "r"(mbar), "r"(parity) : "memory");
    }
}
__device__ __forceinline__ void ldmatrix_x4(uint32_t* r, uint32_t addr) {
    asm volatile("ldmatrix.sync.aligned.m8n8.x4.shared.b16 {%0,%1,%2,%3}, [%4];"
                 : "=r"(r[0]), "=r"(r[1]), "=r"(r[2]), "=r"(r[3]) : "r"(addr));
}
__device__ __forceinline__ void mma16816(float* c, const uint32_t* a,
                                         uint32_t b0, uint32_t b1) {
    asm volatile(
        "mma.sync.aligned.m16n8k16.row.col.f32.f16.f16.f32 "
        "{%0,%1,%2,%3}, {%4,%5,%6,%7}, {%8,%9}, {%0,%1,%2,%3};"
        : "+f"(c[0]), "+f"(c[1]), "+f"(c[2]), "+f"(c[3])
        : "r"(a[0]), "r"(a[1]), "r"(a[2]), "r"(a[3]), "r"(b0), "r"(b1));
}
__device__ __forceinline__ void red_release_add(int* p) {
    asm volatile("red.release.gpu.global.add.s32 [%0], 1;" :: "l"(p) : "memory");
}
__device__ __forceinline__ int ld_acquire_gpu(const int* p) {
    int v;
    asm volatile("ld.acquire.gpu.global.b32 %0, [%1];" : "=r"(v) : "l"(p) : "memory");
    return v;
}

// ============================================================================
// Kernel 0: clear readiness flags (graph-replay safe; runs before k_fused)
// ============================================================================
__global__ void k_clear() {
    if (threadIdx.x < NPANEL) g_xready[threadIdx.x] = 0;
    else if (threadIdx.x < 2 * NPANEL) g_wready[threadIdx.x - NPANEL] = 0;
}

// ============================================================================
// Kernel 1 (fused): prep blocks (bids < B0_GEMM) then GEMM tiles.
// Prep never waits; GEMM CTAs acquire-spin on panel flags. In-order block
// dispatch guarantees every prep block precedes every GEMM block -> no
// deadlock, and later prep overlaps GEMM wave 1.
// ============================================================================
__global__ void __launch_bounds__(256, 2) k_fused(const float4* __restrict__ x,
                                                  const float* __restrict__ w,
                                                  const int* __restrict__ mask,
                                                  const float* __restrict__ bias,
                                                  float* __restrict__ out) {
    extern __shared__ char smem[];
    const int bid = blockIdx.x;
    const int tid = threadIdx.x;

    if (bid < B0_GEMM) {
        // ---------------- prep ----------------
        int conv_block = -1, dens_row = -1;
        if (bid < B0_CONV_EARLY)      dens_row  = bid;
        else if (bid < B0_CONV_REST)  conv_block = bid - B0_CONV_EARLY;
        else if (bid < B0_DENS_REST)  conv_block = CONV_EARLY + (bid - B0_CONV_REST);
        else                          dens_row  = DENS_EARLY + (bid - B0_DENS_REST);

        if (conv_block >= 0) {
            // convert 4 tokens of x: fp32 -> fp16 (MLP=4)
            const int c = conv_block;
            const size_t base = (size_t)c * 1024 + tid;  // float4 units
            float4 v[4];
            #pragma unroll
            for (int i = 0; i < 4; ++i) v[i] = x[base + i * 256];
            __half2* xh2 = reinterpret_cast<__half2*>(g_xh);
            #pragma unroll
            for (int i = 0; i < 4; ++i) {
                const size_t idx = base + i * 256;
                xh2[2 * idx]     = __floats2half2_rn(v[i].x, v[i].y);
                xh2[2 * idx + 1] = __floats2half2_rn(v[i].z, v[i].w);
            }
            __syncthreads();
            if (tid == 0) { __threadfence(); red_release_add(&g_xready[c >> 5]); }
        } else {
            // densify one W row: indices sorted per row; duplicate runs summed
            // in fp32 by the run-leader thread — deterministic, no atomics.
            const int o = dens_row;
            float* acc = reinterpret_cast<float*>(smem);              // 16 KB
            int*   sm  = reinterpret_cast<int*>(smem + IN_F * 4);     // 2 KB
            float* sw  = reinterpret_cast<float*>(smem + IN_F * 4 + NNZ * 4);

            if (tid < NNZ / 4) {
                reinterpret_cast<int4*>(sm)[tid] =
                    reinterpret_cast<const int4*>(mask + (size_t)o * NNZ)[tid];
                reinterpret_cast<float4*>(sw)[tid] =
                    reinterpret_cast<const float4*>(w + (size_t)o * NNZ)[tid];
            }
            #pragma unroll
            for (int i = 0; i < IN_F / 256; ++i) acc[tid + i * 256] = 0.0f;
            __syncthreads();

            #pragma unroll
            for (int jb = 0; jb < NNZ / 256; ++jb) {
                const int j = tid + jb * 256;
                const int m = sm[j];
                if (j > 0 && sm[j - 1] == m) continue;  // not the run leader
                float s = sw[j];
                int jj = j + 1;
                while (jj < NNZ && sm[jj] == m) { s += sw[jj]; jj++; }
                acc[m] = s;  // unique owner, acc pre-zeroed
            }
            __syncthreads();

            __half2* dst = reinterpret_cast<__half2*>(g_wh + (size_t)o * IN_F);
            #pragma unroll
            for (int i = 0; i < IN_F / 512; ++i) {
                const int j = tid + i * 256;
                dst[j] = __floats2half2_rn(acc[2 * j], acc[2 * j + 1]);
            }
            __syncthreads();
            if (tid == 0) { __threadfence(); red_release_add(&g_wready[o >> 7]); }
        }
        return;
    }

    // ---------------- GEMM tile ----------------
    // Compact-corner tile order: first 296 tiles fit in a 32x18 region so
    // wave 1 needs only x panels 0-16 and W panels 0-17 (early prep bids).
    const int g = bid - B0_GEMM;
    int bx, by;
    if (g < 576) { bx = g / 18;        by = g % 18; }
    else         { bx = (g - 576) / 14; by = 18 + (g - 576) % 14; }

    const uint32_t sbase = smem_u32(smem);
    const int wid  = tid >> 5;
    const int lane = tid & 31;
    const int wm = (wid >> 2) * 64;
    const int wn = (wid & 3) * 32;
    const int tok0 = bx * BM;
    const int o0   = by * BN;

    const uint32_t mb_full0  = sbase + MBAR_BASE;
    const uint32_t mb_empty0 = sbase + MBAR_BASE + 24;

    if (tid == 0) {
        #pragma unroll
        for (int s = 0; s < STAGES; ++s) {
            mbar_init(mb_full0 + s * 8, 256);
            mbar_init(mb_empty0 + s * 8, 256);
        }
        // wait until this tile's operand panels are fully produced
        while (ld_acquire_gpu(&g_xready[bx]) < 32)  asm volatile("nanosleep.u32 128;");
        while (ld_acquire_gpu(&g_wready[by]) < 128) asm volatile("nanosleep.u32 128;");
    }
    __syncthreads();  // barriers + panel readiness visible to all threads

    const __half* ga = g_xh + (size_t)tok0 * IN_F;
    const __half* gb = g_wh + (size_t)o0 * IN_F;

    const int ldrow = tid >> 3;
    const int ldc   = (tid & 7) * 16;
    const size_t gkc = (size_t)(ldc >> 1);

    auto load_stage = [&](int it, int s) {
        const uint32_t sA = sbase + s * STAGE_BYTES;
        const uint32_t sB = sA + BM * BK * 2;
        const size_t gk = (size_t)it * BK + gkc;
        #pragma unroll
        for (int i = 0; i < 4; ++i) {
            const int row = ldrow + i * 32;
            const uint32_t off = SW128(row * 128 + ldc);
            cp_async16(sA + off, ga + (size_t)row * IN_F + gk);
            cp_async16(sB + off, gb + (size_t)row * IN_F + gk);
        }
        cp_async_mbar_arrive(mb_full0 + s * 8);
    };

    #pragma unroll
    for (int s = 0; s < STAGES; ++s) load_stage(s, s);

    float acc[4][4][4];
    #pragma unroll
    for (int i = 0; i < 4; ++i)
        #pragma unroll
        for (int j = 0; j < 4; ++j)
            #pragma unroll
            for (int k = 0; k < 4; ++k) acc[i][j][k] = 0.0f;

    const int a_m  = wm + (lane & 15);
    const int a_kb = (lane >> 4) * 16;
    const int b_n  = wn + (lane & 7) + ((lane >> 4) << 3);
    const int b_kb = ((lane >> 3) & 1) * 16;

    for (int j = 0; j < KITERS; ++j) {
        const int cs = j % 3;
        const uint32_t ph = (uint32_t)(j / 3) & 1;
        mbar_wait(mb_full0 + cs * 8, ph);

        const uint32_t sA = sbase + cs * STAGE_BYTES;
        const uint32_t sB = sA + BM * BK * 2;

        #pragma unroll
        for (int ks = 0; ks < BK / 16; ++ks) {
            const int kb = ks * 32;
            uint32_t af[4][4];
            #pragma unroll
            for (int tm = 0; tm < 4; ++tm)
                ldmatrix_x4(af[tm], sA + SW128((a_m + tm * 16) * 128 + kb + a_kb));
            uint32_t bf[2][4];
            #pragma unroll
            for (int tn2 = 0; tn2 < 2; ++tn2)
                ldmatrix_x4(bf[tn2], sB + SW128((b_n + tn2 * 16) * 128 + kb + b_kb));
            if (ks == BK / 16 - 1)
                mbar_arrive(mb_empty0 + cs * 8);
            #pragma unroll
            for (int tm = 0; tm < 4; ++tm)
                #pragma unroll
                for (int tn = 0; tn < 4; ++tn)
                    mma16816(acc[tm][tn], af[tm], bf[tn >> 1][(tn & 1) * 2],
                             bf[tn >> 1][(tn & 1) * 2 + 1]);
        }

        if (j + 3 < KITERS) {
            mbar_wait(mb_empty0 + cs * 8, ph);
            load_stage(j + 3, cs);
        }
    }

    // ---- Epilogue: direct register -> gmem (float2), + bias
    #pragma unroll
    for (int tm = 0; tm < 4; ++tm) {
        const int row = tok0 + wm + tm * 16 + (lane >> 2);
        #pragma unroll
        for (int tn = 0; tn < 4; ++tn) {
            const int col = o0 + wn + tn * 8 + 2 * (lane & 3);
            const float2 bv = *reinterpret_cast<const float2*>(bias + col);
            float2 v0 = {acc[tm][tn][0] + bv.x, acc[tm][tn][1] + bv.y};
            float2 v1 = {acc[tm][tn][2] + bv.x, acc[tm][tn][3] + bv.y};
            *reinterpret_cast<float2*>(out + (size_t)row * OUT_F + col) = v0;
            *reinterpret_cast<float2*>(out + (size_t)(row + 8) * OUT_F + col) = v1;
        }
    }
}

// ============================================================================
// Launch
// ============================================================================
extern "C" void kernel_launch(void* const* d_in, const int* in_sizes, int n_in,
                              void* d_out, int out_size) {
    const float* x    = (const float*)d_in[0];
    const float* w    = (const float*)d_in[1];
    const int*   mask = (const int*)d_in[2];
    const float* bias = (const float*)d_in[3];
    float* out = (float*)d_out;

    cudaFuncSetAttribute(k_fused, cudaFuncAttributeMaxDynamicSharedMemorySize,
                         SMEM_TOTAL);

    k_clear<<<1, 64>>>();
    k_fused<<<GRID, 256, SMEM_TOTAL>>>((const float4*)x, w, mask, bias, out);
}

// round 12
// speedup vs baseline: 1.0531x; 1.0531x over previous
#include <cuda_runtime.h>
#include <cuda_fp16.h>
#include <cstdint>

// ============================================================================
// Problem constants
// ============================================================================
#define T_TOKENS 4096
#define IN_F     4096
#define OUT_F    4096
#define NNZ      512

// GEMM tiling: CTA 128x128, warp tile 64x32 (8 warps, 2x4), 2 CTAs/SM.
static constexpr int BM = 128;
static constexpr int BN = 128;
static constexpr int BK = 64;                 // fp16 -> 128B rows (SW128 atom)
static constexpr int KITERS = IN_F / BK;      // 64
static constexpr int STAGES = 3;
static constexpr int STAGE_BYTES = (BM * BK + BN * BK) * 2;  // 32768
static constexpr int MBAR_BASE  = STAGES * STAGE_BYTES;      // 98304
static constexpr int SMEM_TOTAL = MBAR_BASE + 64;            // 98368

// Prep work items (8192 total), consumed by 296 persistent blocks:
//   conv unit = ONE token (1024 float4 = 4096 floats); 4096 units
//   dens row  = one W row;                             4096 rows
// Panels: x panel p = conv units [128p,128p+128)  (128 tokens)  -> target 128
//         W panel p = dens rows  [128p,128p+128)               -> target 128
// Early ordering interleaves (x panel i, W panel i) pairs for i=0..16, then
// W panel 17, so the compact-corner GEMM tiles unblock earliest-first.
static constexpr int NPREP  = 296;
static constexpr int NPANEL = 32;
static constexpr int E1 = 17 * 256;          // 4352: x/W panel pairs 0..16
static constexpr int E2 = E1 + 128;          // 4480: + W panel 17
static constexpr int E3 = E2 + 15 * 128;     // 6400: + x panels 17..31
static constexpr int NITEMS = 8192;          // + W panels 18..31

// ============================================================================
// Scratch (device globals — no allocation allowed)
// ============================================================================
__device__ __align__(16) __half g_xh[(size_t)T_TOKENS * IN_F];  // 32 MB fp16 x
__device__ __align__(16) __half g_wh[(size_t)OUT_F * IN_F];     // 32 MB fp16 dense W
__device__ int g_xready[NPANEL];  // conv units done per x panel (target 128)
__device__ int g_wready[NPANEL];  // dens rows  done per W panel (target 128)

// ============================================================================
// Helpers
// ============================================================================
__device__ __forceinline__ uint32_t smem_u32(const void* p) {
    uint32_t a;
    asm("{ .reg .u64 t; cvta.to.shared.u64 t, %1; cvt.u32.u64 %0, t; }"
        : "=r"(a) : "l"(p));
    return a;
}
#define SW128(o) ((o) ^ (((o) >> 3) & 0x70))

__device__ __forceinline__ void cp_async16(uint32_t dst, const void* src) {
    asm volatile("cp.async.cg.shared.global [%0], [%1], 16;" :: "r"(dst), "l"(src));
}
__device__ __forceinline__ void cp_async_mbar_arrive(uint32_t mbar) {
    asm volatile("cp.async.mbarrier.arrive.noinc.shared.b64 [%0];"
                 :: "r"(mbar) : "memory");
}
__device__ __forceinline__ void mbar_init(uint32_t mbar, uint32_t cnt) {
    asm volatile("mbarrier.init.shared.b64 [%0], %1;" :: "r"(mbar), "r"(cnt)
                 : "memory");
}
__device__ __forceinline__ void mbar_arrive(uint32_t mbar) {
    asm volatile("mbarrier.arrive.release.cta.shared::cta.b64 _, [%0];"
                 :: "r"(mbar) : "memory");
}
__device__ __forceinline__ void mbar_wait(uint32_t mbar, uint32_t parity) {
    uint32_t done;
    asm volatile("{ .reg .pred p;\n\t"
        "mbarrier.try_wait.parity.acquire.cta.shared::cta.b64 p, [%1], %2;\n\t"
        "selp.b32 %0, 1, 0, p; }"
        : "=r"(done) : "r"(mbar), "r"(parity) : "memory");
    if (!done) {
        asm volatile("{ .reg .pred P1;\n\t"
            "WAIT_LOOP_%=:\n\t"
            "mbarrier.try_wait.parity.acquire.cta.shared::cta.b64 P1, [%0], %1, 0x989680;\n\t"
            "@P1 bra.uni WAIT_DONE_%=;\n\t"
            "bra.uni WAIT_LOOP_%=;\n\t"
            "WAIT_DONE_%=: }"
            :: "r"(mbar), "r"(parity) : "memory");
    }
}
__device__ __forceinline__ void ldmatrix_x4(uint32_t* r, uint32_t addr) {
    asm volatile("ldmatrix.sync.aligned.m8n8.x4.shared.b16 {%0,%1,%2,%3}, [%4];"
                 : "=r"(r[0]), "=r"(r[1]), "=r"(r[2]), "=r"(r[3]) : "r"(addr));
}
__device__ __forceinline__ void mma16816(float* c, const uint32_t* a,
                                         uint32_t b0, uint32_t b1) {
    asm volatile(
        "mma.sync.aligned.m16n8k16.row.col.f32.f16.f16.f32 "
        "{%0,%1,%2,%3}, {%4,%5,%6,%7}, {%8,%9}, {%0,%1,%2,%3};"
        : "+f"(c[0]), "+f"(c[1]), "+f"(c[2]), "+f"(c[3])
        : "r"(a[0]), "r"(a[1]), "r"(a[2]), "r"(a[3]), "r"(b0), "r"(b1));
}
__device__ __forceinline__ void red_release_add(int* p) {
    asm volatile("red.release.gpu.global.add.s32 [%0], 1;" :: "l"(p) : "memory");
}
__device__ __forceinline__ int ld_acquire_gpu(const int* p) {
    int v;
    asm volatile("ld.acquire.gpu.global.b32 %0, [%1];" : "=r"(v) : "l"(p) : "memory");
    return v;
}

// ============================================================================
// Kernel 0: clear readiness flags (graph-replay safe)
// ============================================================================
__global__ void k_clear() {
    if (threadIdx.x < NPANEL) g_xready[threadIdx.x] = 0;
    else if (threadIdx.x < 2 * NPANEL) g_wready[threadIdx.x - NPANEL] = 0;
}

// ============================================================================
// Kernel 1: persistent prep (296 blocks). Fires launch_dependents at start so
// the PDL-attributed GEMM grid is released immediately; prep never waits ->
// no deadlock. Block b consumes items b, b+296, ... (early panels first).
// ============================================================================
__global__ void __launch_bounds__(256) k_prep(const float4* __restrict__ x,
                                              const float* __restrict__ w,
                                              const int* __restrict__ mask) {
    asm volatile("griddepcontrol.launch_dependents;");

    __shared__ float acc[IN_F];   // 16 KB
    __shared__ int   sm_[NNZ];    // 2 KB
    __shared__ float sw_[NNZ];    // 2 KB
    const int tid = threadIdx.x;

    for (int item = blockIdx.x; item < NITEMS; item += NPREP) {
        int conv_unit = -1, dens_row = -1;
        if (item < E1) {
            const int pair = item >> 8, r = item & 255;
            if (r < 128) conv_unit = pair * 128 + r;
            else         dens_row  = pair * 128 + (r - 128);
        } else if (item < E2) dens_row  = 17 * 128 + (item - E1);   // W panel 17
        else if (item < E3)   conv_unit = 17 * 128 + (item - E2);   // x panels 17+
        else                  dens_row  = 18 * 128 + (item - E3);   // W panels 18+

        if (conv_unit >= 0) {
            // convert one token of x: fp32 -> fp16 (1024 float4, MLP=4/thread)
            const size_t base = (size_t)conv_unit * 1024 + tid;
            float4 v[4];
            #pragma unroll
            for (int i = 0; i < 4; ++i) v[i] = x[base + i * 256];
            __half2* xh2 = reinterpret_cast<__half2*>(g_xh);
            #pragma unroll
            for (int i = 0; i < 4; ++i) {
                const size_t idx = base + i * 256;
                xh2[2 * idx]     = __floats2half2_rn(v[i].x, v[i].y);
                xh2[2 * idx + 1] = __floats2half2_rn(v[i].z, v[i].w);
            }
            __syncthreads();  // all threads' stores issued
            if (tid == 0) { __threadfence(); red_release_add(&g_xready[conv_unit >> 7]); }
        } else {
            // densify one W row: indices sorted; duplicate runs summed in fp32
            // by the run-leader thread — deterministic, no atomics.
            const int o = dens_row;
            __syncthreads();  // prior item's smem reads complete before reuse
            if (tid < NNZ / 4) {
                reinterpret_cast<int4*>(sm_)[tid] =
                    reinterpret_cast<const int4*>(mask + (size_t)o * NNZ)[tid];
                reinterpret_cast<float4*>(sw_)[tid] =
                    reinterpret_cast<const float4*>(w + (size_t)o * NNZ)[tid];
            }
            #pragma unroll
            for (int i = 0; i < IN_F / 256; ++i) acc[tid + i * 256] = 0.0f;
            __syncthreads();

            #pragma unroll
            for (int jb = 0; jb < NNZ / 256; ++jb) {
                const int j = tid + jb * 256;
                const int m = sm_[j];
                if (j > 0 && sm_[j - 1] == m) continue;  // not the run leader
                float s = sw_[j];
                int jj = j + 1;
                while (jj < NNZ && sm_[jj] == m) { s += sw_[jj]; jj++; }
                acc[m] = s;  // unique owner, acc pre-zeroed
            }
            __syncthreads();

            __half2* dst = reinterpret_cast<__half2*>(g_wh + (size_t)o * IN_F);
            #pragma unroll
            for (int i = 0; i < IN_F / 512; ++i) {
                const int j = tid + i * 256;
                dst[j] = __floats2half2_rn(acc[2 * j], acc[2 * j + 1]);
            }
            __syncthreads();
            if (tid == 0) { __threadfence(); red_release_add(&g_wready[o >> 7]); }
        }
    }
}

// ============================================================================
// Kernel 2: pipelined fp16 mma.sync GEMM (R9 mainloop) + panel-flag gate.
// PDL-released as soon as all prep blocks start. Compact-corner tile order:
// first-wave tiles need only early panels.
// ============================================================================
__global__ void __launch_bounds__(256, 2) k_gemm(const float* __restrict__ bias,
                                                 float* __restrict__ out) {
    extern __shared__ char smem[];
    const int tid = threadIdx.x;

    const int g = blockIdx.x;
    int bx, by;
    if (g < 576) { bx = g / 18;         by = g % 18; }
    else         { bx = (g - 576) / 14; by = 18 + (g - 576) % 14; }

    const uint32_t sbase = smem_u32(smem);
    const int wid  = tid >> 5;
    const int lane = tid & 31;
    const int wm = (wid >> 2) * 64;
    const int wn = (wid & 3) * 32;
    const int tok0 = bx * BM;
    const int o0   = by * BN;

    const uint32_t mb_full0  = sbase + MBAR_BASE;
    const uint32_t mb_empty0 = sbase + MBAR_BASE + 24;

    if (tid == 0) {
        #pragma unroll
        for (int s = 0; s < STAGES; ++s) {
            mbar_init(mb_full0 + s * 8, 256);
            mbar_init(mb_empty0 + s * 8, 256);
        }
        // gate on this tile's operand panels (128 conv units / 128 dens rows)
        while (ld_acquire_gpu(&g_xready[bx]) < 128) asm volatile("nanosleep.u32 256;");
        while (ld_acquire_gpu(&g_wready[by]) < 128) asm volatile("nanosleep.u32 256;");
    }
    __syncthreads();  // barriers + readiness visible to all threads

    const __half* ga = g_xh + (size_t)tok0 * IN_F;
    const __half* gb = g_wh + (size_t)o0 * IN_F;

    const int ldrow = tid >> 3;
    const int ldc   = (tid & 7) * 16;
    const size_t gkc = (size_t)(ldc >> 1);

    auto load_stage = [&](int it, int s) {
        const uint32_t sA = sbase + s * STAGE_BYTES;
        const uint32_t sB = sA + BM * BK * 2;
        const size_t gk = (size_t)it * BK + gkc;
        #pragma unroll
        for (int i = 0; i < 4; ++i) {
            const int row = ldrow + i * 32;
            const uint32_t off = SW128(row * 128 + ldc);
            cp_async16(sA + off, ga + (size_t)row * IN_F + gk);
            cp_async16(sB + off, gb + (size_t)row * IN_F + gk);
        }
        cp_async_mbar_arrive(mb_full0 + s * 8);
    };

    #pragma unroll
    for (int s = 0; s < STAGES; ++s) load_stage(s, s);

    float acc[4][4][4];
    #pragma unroll
    for (int i = 0; i < 4; ++i)
        #pragma unroll
        for (int j = 0; j < 4; ++j)
            #pragma unroll
            for (int k = 0; k < 4; ++k) acc[i][j][k] = 0.0f;

    const int a_m  = wm + (lane & 15);
    const int a_kb = (lane >> 4) * 16;
    const int b_n  = wn + (lane & 7) + ((lane >> 4) << 3);
    const int b_kb = ((lane >> 3) & 1) * 16;

    for (int j = 0; j < KITERS; ++j) {
        const int cs = j % 3;
        const uint32_t ph = (uint32_t)(j / 3) & 1;
        mbar_wait(mb_full0 + cs * 8, ph);

        const uint32_t sA = sbase + cs * STAGE_BYTES;
        const uint32_t sB = sA + BM * BK * 2;

        #pragma unroll
        for (int ks = 0; ks < BK / 16; ++ks) {
            const int kb = ks * 32;
            uint32_t af[4][4];
            #pragma unroll
            for (int tm = 0; tm < 4; ++tm)
                ldmatrix_x4(af[tm], sA + SW128((a_m + tm * 16) * 128 + kb + a_kb));
            uint32_t bf[2][4];
            #pragma unroll
            for (int tn2 = 0; tn2 < 2; ++tn2)
                ldmatrix_x4(bf[tn2], sB + SW128((b_n + tn2 * 16) * 128 + kb + b_kb));
            if (ks == BK / 16 - 1)
                mbar_arrive(mb_empty0 + cs * 8);
            #pragma unroll
            for (int tm = 0; tm < 4; ++tm)
                #pragma unroll
                for (int tn = 0; tn < 4; ++tn)
                    mma16816(acc[tm][tn], af[tm], bf[tn >> 1][(tn & 1) * 2],
                             bf[tn >> 1][(tn & 1) * 2 + 1]);
        }

        if (j + 3 < KITERS) {
            mbar_wait(mb_empty0 + cs * 8, ph);
            load_stage(j + 3, cs);
        }
    }

    // ---- Epilogue: direct register -> gmem (float2), + bias
    #pragma unroll
    for (int tm = 0; tm < 4; ++tm) {
        const int row = tok0 + wm + tm * 16 + (lane >> 2);
        #pragma unroll
        for (int tn = 0; tn < 4; ++tn) {
            const int col = o0 + wn + tn * 8 + 2 * (lane & 3);
            const float2 bv = *reinterpret_cast<const float2*>(bias + col);
            float2 v0 = {acc[tm][tn][0] + bv.x, acc[tm][tn][1] + bv.y};
            float2 v1 = {acc[tm][tn][2] + bv.x, acc[tm][tn][3] + bv.y};
            *reinterpret_cast<float2*>(out + (size_t)row * OUT_F + col) = v0;
            *reinterpret_cast<float2*>(out + (size_t)(row + 8) * OUT_F + col) = v1;
        }
    }
}

// ============================================================================
// Launch: k_clear -> k_prep -> k_gemm (PDL; panel flags give fine ordering).
// If the runtime serializes instead, behavior degrades to R9 (~310 us).
// ============================================================================
extern "C" void kernel_launch(void* const* d_in, const int* in_sizes, int n_in,
                              void* d_out, int out_size) {
    const float* x    = (const float*)d_in[0];
    const float* w    = (const float*)d_in[1];
    const int*   mask = (const int*)d_in[2];
    const float* bias = (const float*)d_in[3];
    float* out = (float*)d_out;

    cudaFuncSetAttribute(k_gemm, cudaFuncAttributeMaxDynamicSharedMemorySize,
                         SMEM_TOTAL);

    k_clear<<<1, 64>>>();
    k_prep<<<NPREP, 256>>>((const float4*)x, w, mask);

    cudaLaunchConfig_t cfg = {};
    cfg.gridDim  = dim3(1024, 1, 1);
    cfg.blockDim = dim3(256, 1, 1);
    cfg.dynamicSmemBytes = SMEM_TOTAL;
    cfg.stream = 0;
    cudaLaunchAttribute attr[1];
    attr[0].id = cudaLaunchAttributeProgrammaticStreamSerialization;
    attr[0].val.programmaticStreamSerializationAllowed = 1;
    cfg.attrs = attr;
    cfg.numAttrs = 1;
    cudaLaunchKernelEx(&cfg, k_gemm, bias, out);
}

// round 14
// speedup vs baseline: 1.1273x; 1.0705x over previous
#include <cuda_runtime.h>
#include <cuda_fp16.h>
#include <cstdint>

// ============================================================================
// Problem constants
// ============================================================================
#define T_TOKENS 4096
#define IN_F     4096
#define OUT_F    4096
#define NNZ      512

// GEMM tiling: CTA 128x128, warp tile 64x32 (8 warps, 2x4), 2 CTAs/SM.
static constexpr int BM = 128;
static constexpr int BN = 128;
static constexpr int BK = 64;                 // fp16 -> 128B rows (SW128 atom)
static constexpr int KITERS = IN_F / BK;      // 64
static constexpr int STAGES = 3;
static constexpr int STAGE_BYTES = (BM * BK + BN * BK) * 2;  // 32768
static constexpr int MBAR_BASE  = STAGES * STAGE_BYTES;      // 98304
static constexpr int SMEM_TOTAL = MBAR_BASE + 64;            // 98368

// prep: conv blocks do 8 float4 per thread (MLP=8)
static constexpr int CONV_BLOCKS = (T_TOKENS * IN_F / 4) / (256 * 8);  // 2048

// ============================================================================
// Scratch (device globals — no allocation allowed)
// ============================================================================
__device__ __align__(16) __half g_xh[(size_t)T_TOKENS * IN_F];  // 32 MB fp16 x
__device__ __align__(16) __half g_wh[(size_t)OUT_F * IN_F];     // 32 MB fp16 dense W

// ============================================================================
// Helpers
// ============================================================================
__device__ __forceinline__ uint32_t smem_u32(const void* p) {
    uint32_t a;
    asm("{ .reg .u64 t; cvta.to.shared.u64 t, %1; cvt.u32.u64 %0, t; }"
        : "=r"(a) : "l"(p));
    return a;
}
#define SW128(o) ((o) ^ (((o) >> 3) & 0x70))

__device__ __forceinline__ void cp_async16(uint32_t dst, const void* src) {
    asm volatile("cp.async.cg.shared.global [%0], [%1], 16;" :: "r"(dst), "l"(src));
}
__device__ __forceinline__ void cp_async_mbar_arrive(uint32_t mbar) {
    asm volatile("cp.async.mbarrier.arrive.noinc.shared.b64 [%0];"
                 :: "r"(mbar) : "memory");
}
__device__ __forceinline__ void mbar_init(uint32_t mbar, uint32_t cnt) {
    asm volatile("mbarrier.init.shared.b64 [%0], %1;" :: "r"(mbar), "r"(cnt)
                 : "memory");
}
__device__ __forceinline__ void mbar_arrive(uint32_t mbar) {
    asm volatile("mbarrier.arrive.release.cta.shared::cta.b64 _, [%0];"
                 :: "r"(mbar) : "memory");
}
__device__ __forceinline__ void mbar_wait(uint32_t mbar, uint32_t parity) {
    uint32_t done;
    asm volatile("{ .reg .pred p;\n\t"
        "mbarrier.try_wait.parity.acquire.cta.shared::cta.b64 p, [%1], %2;\n\t"
        "selp.b32 %0, 1, 0, p; }"
        : "=r"(done) : "r"(mbar), "r"(parity) : "memory");
    if (!done) {
        asm volatile("{ .reg .pred P1;\n\t"
            "WAIT_LOOP_%=:\n\t"
            "mbarrier.try_wait.parity.acquire.cta.shared::cta.b64 P1, [%0], %1, 0x989680;\n\t"
            "@P1 bra.uni WAIT_DONE_%=;\n\t"
            "bra.uni WAIT_LOOP_%=;\n\t"
            "WAIT_DONE_%=: }"
            :: "r"(mbar), "r"(parity) : "memory");
    }
}
__device__ __forceinline__ void ldmatrix_x4(uint32_t* r, uint32_t addr) {
    asm volatile("ldmatrix.sync.aligned.m8n8.x4.shared.b16 {%0,%1,%2,%3}, [%4];"
                 : "=r"(r[0]), "=r"(r[1]), "=r"(r[2]), "=r"(r[3]) : "r"(addr));
}
__device__ __forceinline__ void mma16816(float* c, const uint32_t* a,
                                         uint32_t b0, uint32_t b1) {
    asm volatile(
        "mma.sync.aligned.m16n8k16.row.col.f32.f16.f16.f32 "
        "{%0,%1,%2,%3}, {%4,%5,%6,%7}, {%8,%9}, {%0,%1,%2,%3};"
        : "+f"(c[0]), "+f"(c[1]), "+f"(c[2]), "+f"(c[3])
        : "r"(a[0]), "r"(a[1]), "r"(a[2]), "r"(a[3]), "r"(b0), "r"(b1));
}
__device__ __forceinline__ float4 ldcs4(const float4* p) {
    float4 v;
    asm volatile("ld.global.cs.v4.f32 {%0,%1,%2,%3}, [%4];"
                 : "=f"(v.x), "=f"(v.y), "=f"(v.z), "=f"(v.w) : "l"(p));
    return v;
}
__device__ __forceinline__ int4 ldcs4i(const int4* p) {
    int4 v;
    asm volatile("ld.global.cs.v4.b32 {%0,%1,%2,%3}, [%4];"
                 : "=r"(v.x), "=r"(v.y), "=r"(v.z), "=r"(v.w) : "l"(p));
    return v;
}
__device__ __forceinline__ uint32_t h2_bits(__half2 h) {
    uint32_t u;
    memcpy(&u, &h, 4);
    return u;
}

// ============================================================================
// Kernel 1 (fused prep):
//   blocks [0, CONV_BLOCKS): convert x fp32->fp16, 8 independent float4 per
//   thread (MLP=8), x read with .cs (read-once, keep L2 for g_xh/g_wh).
//   blocks [CONV_BLOCKS, +OUT_F): densify one W row each. Vectorized smem
//   zero-fill (float4) and packed 16B/8B g_wh stores cut per-row latency.
// ============================================================================
__global__ void __launch_bounds__(256) k_prep(const float4* __restrict__ x,
                                              const float* __restrict__ w,
                                              const int* __restrict__ mask) {
    if (blockIdx.x < CONV_BLOCKS) {
        const size_t base = (size_t)blockIdx.x * (256 * 8) + threadIdx.x;
        float4 v[8];
        #pragma unroll
        for (int i = 0; i < 8; ++i) v[i] = ldcs4(&x[base + i * 256]);
        __half2* xh2 = reinterpret_cast<__half2*>(g_xh);
        #pragma unroll
        for (int i = 0; i < 8; ++i) {
            const size_t idx = base + i * 256;
            xh2[2 * idx]     = __floats2half2_rn(v[i].x, v[i].y);
            xh2[2 * idx + 1] = __floats2half2_rn(v[i].z, v[i].w);
        }
        return;
    }
    // ---- densify: indices sorted per row; duplicate runs summed in fp32 by
    // the run-leader thread — deterministic, no atomics.
    __shared__ __align__(16) float acc[IN_F];   // 16 KB
    __shared__ __align__(16) int   sm_[NNZ];    // 2 KB staged mask row
    __shared__ __align__(16) float sw_[NNZ];    // 2 KB staged weight row
    const int o = blockIdx.x - CONV_BLOCKS;
    const int tid = threadIdx.x;

    // stage mask/w rows (vectorized, .cs: read-once)
    if (tid < NNZ / 4) {
        reinterpret_cast<int4*>(sm_)[tid] =
            ldcs4i(reinterpret_cast<const int4*>(mask + (size_t)o * NNZ) + tid);
        reinterpret_cast<float4*>(sw_)[tid] =
            ldcs4(reinterpret_cast<const float4*>(w + (size_t)o * NNZ) + tid);
    }
    // zero-fill acc with float4 stores (4 rounds)
    {
        float4* a4 = reinterpret_cast<float4*>(acc);
        const float4 z = {0.f, 0.f, 0.f, 0.f};
        #pragma unroll
        for (int i = 0; i < IN_F / 4 / 256; ++i) a4[tid + i * 256] = z;
    }
    __syncthreads();

    #pragma unroll
    for (int jb = 0; jb < NNZ / 256; ++jb) {
        const int j = tid + jb * 256;
        const int m = sm_[j];
        if (j > 0 && sm_[j - 1] == m) continue;  // not the run leader
        float s = sw_[j];
        int jj = j + 1;
        while (jj < NNZ && sm_[jj] == m) { s += sw_[jj]; jj++; }
        acc[m] = s;  // unique owner, acc pre-zeroed
    }
    __syncthreads();

    // convert + store 4 halves (8B) per round, 4 rounds per thread
    {
        uint2* dst = reinterpret_cast<uint2*>(g_wh + (size_t)o * IN_F);
        #pragma unroll
        for (int i = 0; i < IN_F / 4 / 256; ++i) {
            const int q = tid + i * 256;            // 4-half group index
            uint2 pk;
            pk.x = h2_bits(__floats2half2_rn(acc[4 * q],     acc[4 * q + 1]));
            pk.y = h2_bits(__floats2half2_rn(acc[4 * q + 2], acc[4 * q + 3]));
            dst[q] = pk;
        }
    }
}

// ============================================================================
// Kernel 2: pipelined fp16 mma.sync GEMM (R9 configuration — best measured).
//   out[T,O] = xh[T,In] * Wh[O,In]^T + bias
// CTA 128x128, BK=64, 3-stage mbarrier ring, 8 warps @ 64x32, 2 CTAs/SM.
// full[s] tracks cp.async completion; empty[s] tracks all-warps-done-reading.
// ============================================================================
__global__ void __launch_bounds__(256, 2) k_gemm(const float* __restrict__ bias,
                                                 float* __restrict__ out) {
    extern __shared__ char smem[];
    const uint32_t sbase = smem_u32(smem);
    const int tid  = threadIdx.x;
    const int wid  = tid >> 5;
    const int lane = tid & 31;
    const int wm = (wid >> 2) * 64;   // warp row offset
    const int wn = (wid & 3) * 32;    // warp col offset
    const int tok0 = blockIdx.x * BM;
    const int o0   = blockIdx.y * BN;

    const uint32_t mb_full0  = sbase + MBAR_BASE;
    const uint32_t mb_empty0 = sbase + MBAR_BASE + 24;

    if (tid == 0) {
        #pragma unroll
        for (int s = 0; s < STAGES; ++s) {
            mbar_init(mb_full0 + s * 8, 256);
            mbar_init(mb_empty0 + s * 8, 256);
        }
    }
    __syncthreads();  // barriers visible before any use

    const __half* ga = g_xh + (size_t)tok0 * IN_F;
    const __half* gb = g_wh + (size_t)o0 * IN_F;

    const int ldrow = tid >> 3;        // 0..31
    const int ldc   = (tid & 7) * 16;  // byte offset within 128B row
    const size_t gkc = (size_t)(ldc >> 1);

    auto load_stage = [&](int it, int s) {
        const uint32_t sA = sbase + s * STAGE_BYTES;
        const uint32_t sB = sA + BM * BK * 2;
        const size_t gk = (size_t)it * BK + gkc;
        #pragma unroll
        for (int i = 0; i < 4; ++i) {
            const int row = ldrow + i * 32;
            const uint32_t off = SW128(row * 128 + ldc);
            cp_async16(sA + off, ga + (size_t)row * IN_F + gk);
            cp_async16(sB + off, gb + (size_t)row * IN_F + gk);
        }
        cp_async_mbar_arrive(mb_full0 + s * 8);
    };

    #pragma unroll
    for (int s = 0; s < STAGES; ++s) load_stage(s, s);

    float acc[4][4][4];
    #pragma unroll
    for (int i = 0; i < 4; ++i)
        #pragma unroll
        for (int j = 0; j < 4; ++j)
            #pragma unroll
            for (int k = 0; k < 4; ++k) acc[i][j][k] = 0.0f;

    const int a_m  = wm + (lane & 15);
    const int a_kb = (lane >> 4) * 16;
    const int b_n  = wn + (lane & 7) + ((lane >> 4) << 3);
    const int b_kb = ((lane >> 3) & 1) * 16;

    for (int j = 0; j < KITERS; ++j) {
        const int cs = j % 3;
        const uint32_t ph = (uint32_t)(j / 3) & 1;
        mbar_wait(mb_full0 + cs * 8, ph);

        const uint32_t sA = sbase + cs * STAGE_BYTES;
        const uint32_t sB = sA + BM * BK * 2;

        #pragma unroll
        for (int ks = 0; ks < BK / 16; ++ks) {
            const int kb = ks * 32;
            uint32_t af[4][4];
            #pragma unroll
            for (int tm = 0; tm < 4; ++tm)
                ldmatrix_x4(af[tm], sA + SW128((a_m + tm * 16) * 128 + kb + a_kb));
            uint32_t bf[2][4];
            #pragma unroll
            for (int tn2 = 0; tn2 < 2; ++tn2)
                ldmatrix_x4(bf[tn2], sB + SW128((b_n + tn2 * 16) * 128 + kb + b_kb));
            if (ks == BK / 16 - 1)
                mbar_arrive(mb_empty0 + cs * 8);  // all my reads of stage cs done
            #pragma unroll
            for (int tm = 0; tm < 4; ++tm)
                #pragma unroll
                for (int tn = 0; tn < 4; ++tn)
                    mma16816(acc[tm][tn], af[tm], bf[tn >> 1][(tn & 1) * 2],
                             bf[tn >> 1][(tn & 1) * 2 + 1]);
        }

        if (j + 3 < KITERS) {
            mbar_wait(mb_empty0 + cs * 8, ph);  // all warps done reading stage cs
            load_stage(j + 3, cs);
        }
    }

    // ---- Epilogue: direct register -> gmem (float2), + bias
    #pragma unroll
    for (int tm = 0; tm < 4; ++tm) {
        const int row = tok0 + wm + tm * 16 + (lane >> 2);
        #pragma unroll
        for (int tn = 0; tn < 4; ++tn) {
            const int col = o0 + wn + tn * 8 + 2 * (lane & 3);
            const float2 bv = *reinterpret_cast<const float2*>(bias + col);
            float2 v0 = {acc[tm][tn][0] + bv.x, acc[tm][tn][1] + bv.y};
            float2 v1 = {acc[tm][tn][2] + bv.x, acc[tm][tn][3] + bv.y};
            *reinterpret_cast<float2*>(out + (size_t)row * OUT_F + col) = v0;
            *reinterpret_cast<float2*>(out + (size_t)(row + 8) * OUT_F + col) = v1;
        }
    }
}

// ============================================================================
// Launch
// ============================================================================
extern "C" void kernel_launch(void* const* d_in, const int* in_sizes, int n_in,
                              void* d_out, int out_size) {
    const float* x    = (const float*)d_in[0];
    const float* w    = (const float*)d_in[1];
    const int*   mask = (const int*)d_in[2];
    const float* bias = (const float*)d_in[3];
    float* out = (float*)d_out;

    cudaFuncSetAttribute(k_gemm, cudaFuncAttributeMaxDynamicSharedMemorySize,
                         SMEM_TOTAL);

    k_prep<<<CONV_BLOCKS + OUT_F, 256>>>((const float4*)x, w, mask);
    k_gemm<<<dim3(T_TOKENS / BM, OUT_F / BN), 256, SMEM_TOTAL>>>(bias, out);
}

// round 15
// speedup vs baseline: 1.1344x; 1.0063x over previous
#include <cuda_runtime.h>
#include <cuda_fp16.h>
#include <cstdint>

// ============================================================================
// Problem constants
// ============================================================================
#define T_TOKENS 4096
#define IN_F     4096
#define OUT_F    4096
#define NNZ      512

// GEMM tiling: CTA 128x128, warp tile 64x32 (8 warps, 2x4), 2 CTAs/SM.
static constexpr int BM = 128;
static constexpr int BN = 128;
static constexpr int BK = 64;                 // fp16 -> 128B rows (SW128 atom)
static constexpr int KITERS = IN_F / BK;      // 64
static constexpr int STAGES = 3;
static constexpr int STAGE_BYTES = (BM * BK + BN * BK) * 2;  // 32768
static constexpr int MBAR_BASE  = STAGES * STAGE_BYTES;      // 98304
static constexpr int SMEM_TOTAL = MBAR_BASE + 64;            // 98368

// prep: conv blocks do 8 float4 per thread (MLP=8)
static constexpr int CONV_BLOCKS = (T_TOKENS * IN_F / 4) / (256 * 8);  // 2048

// ============================================================================
// Scratch (device globals — no allocation allowed)
// ============================================================================
__device__ __align__(16) __half g_xh[(size_t)T_TOKENS * IN_F];  // 32 MB fp16 x
__device__ __align__(16) __half g_wh[(size_t)OUT_F * IN_F];     // 32 MB fp16 dense W

// ============================================================================
// Helpers
// ============================================================================
__device__ __forceinline__ uint32_t smem_u32(const void* p) {
    uint32_t a;
    asm("{ .reg .u64 t; cvta.to.shared.u64 t, %1; cvt.u32.u64 %0, t; }"
        : "=r"(a) : "l"(p));
    return a;
}
#define SW128(o) ((o) ^ (((o) >> 3) & 0x70))

__device__ __forceinline__ void cp_async16(uint32_t dst, const void* src) {
    asm volatile("cp.async.cg.shared.global [%0], [%1], 16;" :: "r"(dst), "l"(src));
}
__device__ __forceinline__ void cp_async_mbar_arrive(uint32_t mbar) {
    asm volatile("cp.async.mbarrier.arrive.noinc.shared.b64 [%0];"
                 :: "r"(mbar) : "memory");
}
__device__ __forceinline__ void mbar_init(uint32_t mbar, uint32_t cnt) {
    asm volatile("mbarrier.init.shared.b64 [%0], %1;" :: "r"(mbar), "r"(cnt)
                 : "memory");
}
__device__ __forceinline__ void mbar_arrive(uint32_t mbar) {
    asm volatile("mbarrier.arrive.release.cta.shared::cta.b64 _, [%0];"
                 :: "r"(mbar) : "memory");
}
__device__ __forceinline__ void mbar_wait(uint32_t mbar, uint32_t parity) {
    uint32_t done;
    asm volatile("{ .reg .pred p;\n\t"
        "mbarrier.try_wait.parity.acquire.cta.shared::cta.b64 p, [%1], %2;\n\t"
        "selp.b32 %0, 1, 0, p; }"
        : "=r"(done) : "r"(mbar), "r"(parity) : "memory");
    if (!done) {
        asm volatile("{ .reg .pred P1;\n\t"
            "WAIT_LOOP_%=:\n\t"
            "mbarrier.try_wait.parity.acquire.cta.shared::cta.b64 P1, [%0], %1, 0x989680;\n\t"
            "@P1 bra.uni WAIT_DONE_%=;\n\t"
            "bra.uni WAIT_LOOP_%=;\n\t"
            "WAIT_DONE_%=: }"
            :: "r"(mbar), "r"(parity) : "memory");
    }
}
__device__ __forceinline__ void ldmatrix_x4(uint32_t* r, uint32_t addr) {
    asm volatile("ldmatrix.sync.aligned.m8n8.x4.shared.b16 {%0,%1,%2,%3}, [%4];"
                 : "=r"(r[0]), "=r"(r[1]), "=r"(r[2]), "=r"(r[3]) : "r"(addr));
}
__device__ __forceinline__ void mma16816(float* c, const uint32_t* a,
                                         uint32_t b0, uint32_t b1) {
    asm volatile(
        "mma.sync.aligned.m16n8k16.row.col.f32.f16.f16.f32 "
        "{%0,%1,%2,%3}, {%4,%5,%6,%7}, {%8,%9}, {%0,%1,%2,%3};"
        : "+f"(c[0]), "+f"(c[1]), "+f"(c[2]), "+f"(c[3])
        : "r"(a[0]), "r"(a[1]), "r"(a[2]), "r"(a[3]), "r"(b0), "r"(b1));
}
__device__ __forceinline__ float4 ldcs4(const float4* p) {
    float4 v;
    asm volatile("ld.global.cs.v4.f32 {%0,%1,%2,%3}, [%4];"
                 : "=f"(v.x), "=f"(v.y), "=f"(v.z), "=f"(v.w) : "l"(p));
    return v;
}
__device__ __forceinline__ int4 ldcs4i(const int4* p) {
    int4 v;
    asm volatile("ld.global.cs.v4.b32 {%0,%1,%2,%3}, [%4];"
                 : "=r"(v.x), "=r"(v.y), "=r"(v.z), "=r"(v.w) : "l"(p));
    return v;
}
__device__ __forceinline__ uint32_t h2_bits(__half2 h) {
    uint32_t u;
    memcpy(&u, &h, 4);
    return u;
}

// ============================================================================
// Kernel 1 (fused prep):
//   blocks [0, CONV_BLOCKS): convert x fp32->fp16, 8 independent float4 per
//   thread (MLP=8), x read with .cs (read-once, keep L2 for g_xh/g_wh).
//   blocks [CONV_BLOCKS, +OUT_F): densify one W row each. Vectorized smem
//   zero-fill (float4) and packed 8B g_wh stores cut per-row latency.
// ============================================================================
__global__ void __launch_bounds__(256) k_prep(const float4* __restrict__ x,
                                              const float* __restrict__ w,
                                              const int* __restrict__ mask) {
    if (blockIdx.x < CONV_BLOCKS) {
        const size_t base = (size_t)blockIdx.x * (256 * 8) + threadIdx.x;
        float4 v[8];
        #pragma unroll
        for (int i = 0; i < 8; ++i) v[i] = ldcs4(&x[base + i * 256]);
        __half2* xh2 = reinterpret_cast<__half2*>(g_xh);
        #pragma unroll
        for (int i = 0; i < 8; ++i) {
            const size_t idx = base + i * 256;
            xh2[2 * idx]     = __floats2half2_rn(v[i].x, v[i].y);
            xh2[2 * idx + 1] = __floats2half2_rn(v[i].z, v[i].w);
        }
        return;
    }
    // ---- densify: indices sorted per row; duplicate runs summed in fp32 by
    // the run-leader thread — deterministic, no atomics.
    __shared__ __align__(16) float acc[IN_F];   // 16 KB
    __shared__ __align__(16) int   sm_[NNZ];    // 2 KB staged mask row
    __shared__ __align__(16) float sw_[NNZ];    // 2 KB staged weight row
    const int o = blockIdx.x - CONV_BLOCKS;
    const int tid = threadIdx.x;

    // stage mask/w rows (vectorized, .cs: read-once)
    if (tid < NNZ / 4) {
        reinterpret_cast<int4*>(sm_)[tid] =
            ldcs4i(reinterpret_cast<const int4*>(mask + (size_t)o * NNZ) + tid);
        reinterpret_cast<float4*>(sw_)[tid] =
            ldcs4(reinterpret_cast<const float4*>(w + (size_t)o * NNZ) + tid);
    }
    // zero-fill acc with float4 stores (4 rounds)
    {
        float4* a4 = reinterpret_cast<float4*>(acc);
        const float4 z = {0.f, 0.f, 0.f, 0.f};
        #pragma unroll
        for (int i = 0; i < IN_F / 4 / 256; ++i) a4[tid + i * 256] = z;
    }
    __syncthreads();

    #pragma unroll
    for (int jb = 0; jb < NNZ / 256; ++jb) {
        const int j = tid + jb * 256;
        const int m = sm_[j];
        if (j > 0 && sm_[j - 1] == m) continue;  // not the run leader
        float s = sw_[j];
        int jj = j + 1;
        while (jj < NNZ && sm_[jj] == m) { s += sw_[jj]; jj++; }
        acc[m] = s;  // unique owner, acc pre-zeroed
    }
    __syncthreads();

    // convert + store 4 halves (8B) per round, 4 rounds per thread
    {
        uint2* dst = reinterpret_cast<uint2*>(g_wh + (size_t)o * IN_F);
        #pragma unroll
        for (int i = 0; i < IN_F / 4 / 256; ++i) {
            const int q = tid + i * 256;            // 4-half group index
            uint2 pk;
            pk.x = h2_bits(__floats2half2_rn(acc[4 * q],     acc[4 * q + 1]));
            pk.y = h2_bits(__floats2half2_rn(acc[4 * q + 2], acc[4 * q + 3]));
            dst[q] = pk;
        }
    }
}

// ============================================================================
// Kernel 2: pipelined fp16 mma.sync GEMM.
//   out[T,O] = xh[T,In] * Wh[O,In]^T + bias
// CTA 128x128, BK=64, 3-stage mbarrier ring, 8 warps @ 64x32, 2 CTAs/SM.
// full[s]: cp.async async-path arrivals (count 256, noinc).
// empty[s]: count 8 — ONE arrive per warp (lane 0) after the warp's last
// LDSM of the stage. ldmatrix is warp-collective and retires in order, so
// lane 0's arrive.release orders the whole warp's stage reads before the
// producer's acquire-wait + overwrite. Cuts single-address smem-atomic
// barrier traffic 32x (~256 cy/iter -> ~8 cy/iter).
// ============================================================================
__global__ void __launch_bounds__(256, 2) k_gemm(const float* __restrict__ bias,
                                                 float* __restrict__ out) {
    extern __shared__ char smem[];
    const uint32_t sbase = smem_u32(smem);
    const int tid  = threadIdx.x;
    const int wid  = tid >> 5;
    const int lane = tid & 31;
    const int wm = (wid >> 2) * 64;   // warp row offset
    const int wn = (wid & 3) * 32;    // warp col offset
    const int tok0 = blockIdx.x * BM;
    const int o0   = blockIdx.y * BN;

    const uint32_t mb_full0  = sbase + MBAR_BASE;
    const uint32_t mb_empty0 = sbase + MBAR_BASE + 24;

    if (tid == 0) {
        #pragma unroll
        for (int s = 0; s < STAGES; ++s) {
            mbar_init(mb_full0 + s * 8, 256);   // cp.async arrivals (all threads)
            mbar_init(mb_empty0 + s * 8, 8);    // one arrive per warp
        }
    }
    __syncthreads();  // barriers visible before any use

    const __half* ga = g_xh + (size_t)tok0 * IN_F;
    const __half* gb = g_wh + (size_t)o0 * IN_F;

    const int ldrow = tid >> 3;        // 0..31
    const int ldc   = (tid & 7) * 16;  // byte offset within 128B row
    const size_t gkc = (size_t)(ldc >> 1);

    auto load_stage = [&](int it, int s) {
        const uint32_t sA = sbase + s * STAGE_BYTES;
        const uint32_t sB = sA + BM * BK * 2;
        const size_t gk = (size_t)it * BK + gkc;
        #pragma unroll
        for (int i = 0; i < 4; ++i) {
            const int row = ldrow + i * 32;
            const uint32_t off = SW128(row * 128 + ldc);
            cp_async16(sA + off, ga + (size_t)row * IN_F + gk);
            cp_async16(sB + off, gb + (size_t)row * IN_F + gk);
        }
        cp_async_mbar_arrive(mb_full0 + s * 8);
    };

    #pragma unroll
    for (int s = 0; s < STAGES; ++s) load_stage(s, s);

    float acc[4][4][4];
    #pragma unroll
    for (int i = 0; i < 4; ++i)
        #pragma unroll
        for (int j = 0; j < 4; ++j)
            #pragma unroll
            for (int k = 0; k < 4; ++k) acc[i][j][k] = 0.0f;

    const int a_m  = wm + (lane & 15);
    const int a_kb = (lane >> 4) * 16;
    const int b_n  = wn + (lane & 7) + ((lane >> 4) << 3);
    const int b_kb = ((lane >> 3) & 1) * 16;

    for (int j = 0; j < KITERS; ++j) {
        const int cs = j % 3;
        const uint32_t ph = (uint32_t)(j / 3) & 1;
        mbar_wait(mb_full0 + cs * 8, ph);

        const uint32_t sA = sbase + cs * STAGE_BYTES;
        const uint32_t sB = sA + BM * BK * 2;

        #pragma unroll
        for (int ks = 0; ks < BK / 16; ++ks) {
            const int kb = ks * 32;
            uint32_t af[4][4];
            #pragma unroll
            for (int tm = 0; tm < 4; ++tm)
                ldmatrix_x4(af[tm], sA + SW128((a_m + tm * 16) * 128 + kb + a_kb));
            uint32_t bf[2][4];
            #pragma unroll
            for (int tn2 = 0; tn2 < 2; ++tn2)
                ldmatrix_x4(bf[tn2], sB + SW128((b_n + tn2 * 16) * 128 + kb + b_kb));
            if (ks == BK / 16 - 1 && lane == 0)
                mbar_arrive(mb_empty0 + cs * 8);  // warp's stage reads all done
            #pragma unroll
            for (int tm = 0; tm < 4; ++tm)
                #pragma unroll
                for (int tn = 0; tn < 4; ++tn)
                    mma16816(acc[tm][tn], af[tm], bf[tn >> 1][(tn & 1) * 2],
                             bf[tn >> 1][(tn & 1) * 2 + 1]);
        }

        if (j + 3 < KITERS) {
            mbar_wait(mb_empty0 + cs * 8, ph);  // all 8 warps done reading cs
            load_stage(j + 3, cs);
        }
    }

    // ---- Epilogue: direct register -> gmem (float2), + bias
    #pragma unroll
    for (int tm = 0; tm < 4; ++tm) {
        const int row = tok0 + wm + tm * 16 + (lane >> 2);
        #pragma unroll
        for (int tn = 0; tn < 4; ++tn) {
            const int col = o0 + wn + tn * 8 + 2 * (lane & 3);
            const float2 bv = *reinterpret_cast<const float2*>(bias + col);
            float2 v0 = {acc[tm][tn][0] + bv.x, acc[tm][tn][1] + bv.y};
            float2 v1 = {acc[tm][tn][2] + bv.x, acc[tm][tn][3] + bv.y};
            *reinterpret_cast<float2*>(out + (size_t)row * OUT_F + col) = v0;
            *reinterpret_cast<float2*>(out + (size_t)(row + 8) * OUT_F + col) = v1;
        }
    }
}

// ============================================================================
// Launch
// ============================================================================
extern "C" void kernel_launch(void* const* d_in, const int* in_sizes, int n_in,
                              void* d_out, int out_size) {
    const float* x    = (const float*)d_in[0];
    const float* w    = (const float*)d_in[1];
    const int*   mask = (const int*)d_in[2];
    const float* bias = (const float*)d_in[3];
    float* out = (float*)d_out;

    cudaFuncSetAttribute(k_gemm, cudaFuncAttributeMaxDynamicSharedMemorySize,
                         SMEM_TOTAL);

    k_prep<<<CONV_BLOCKS + OUT_F, 256>>>((const float4*)x, w, mask);
    k_gemm<<<dim3(T_TOKENS / BM, OUT_F / BN), 256, SMEM_TOTAL>>>(bias, out);
}